// round 2
// baseline (speedup 1.0000x reference)
#include <cuda_runtime.h>
#include <cstdint>

#define N_NODES 100000
#define N_EDGES 800000
#define H 128
#define HH (H*H)

// ---- scratch (no cudaMalloc allowed) ----
__device__ float g_bufA[N_NODES * H];
__device__ float g_bufB[N_NODES * H];
__device__ float g_Pl[N_NODES * H];
__device__ float g_Pr[N_NODES * H];
__device__ float g_inv[N_NODES];

// ---------------- degree ----------------
__global__ void k_deg(const int* __restrict__ dst, float* __restrict__ deg) {
    int e = blockIdx.x * 256 + threadIdx.x;
    if (e < N_EDGES) atomicAdd(deg + dst[e], 1.0f);
}
__global__ void k_inv(float* __restrict__ d) {
    int i = blockIdx.x * 256 + threadIdx.x;
    if (i < N_NODES) { float v = d[i]; d[i] = v > 0.f ? 1.f / v : 0.f; }
}

// ---------------- node projection: h = x @ W + b  (K=5) ----------------
__global__ void k_nodeproj(const float* __restrict__ x, const float* __restrict__ W,
                           const float* __restrict__ b, float* __restrict__ h) {
    int idx = blockIdx.x * 256 + threadIdx.x;
    if (idx >= N_NODES * H) return;
    int n = idx >> 7, j = idx & 127;
    float acc = b[j];
#pragma unroll
    for (int k = 0; k < 5; k++) acc = fmaf(x[n * 5 + k], W[k * H + j], acc);
    h[idx] = acc;
}

// ---------------- scatter-add: agg[dst] += h[src], warp per edge ----------------
__global__ void k_scatter(const int* __restrict__ src, const int* __restrict__ dst,
                          const float* __restrict__ h, float* __restrict__ agg) {
    int w = (blockIdx.x * blockDim.x + threadIdx.x) >> 5;
    int lane = threadIdx.x & 31;
    if (w >= N_EDGES) return;
    int s = src[w], d = dst[w];
    float4 v = ((const float4*)(h + (size_t)s * H))[lane];
    float* p = agg + (size_t)d * H + lane * 4;
    asm volatile("red.global.add.v4.f32 [%0], {%1,%2,%3,%4};"
                 :: "l"(p), "f"(v.x), "f"(v.y), "f"(v.z), "f"(v.w) : "memory");
}

// ---------------- fused SAGE GEMM: t = (agg*inv)@Wl + bl + h@Wr, in-place into agg ----
// BM=64, BN=128, K=256 (4 chunks mean + 4 chunks h), 256 threads, thread tile 8x4
__global__ void __launch_bounds__(256) k_sage(
    const float* __restrict__ hX, float* __restrict__ aggY,
    const float* __restrict__ Wl, const float* __restrict__ bl,
    const float* __restrict__ Wr, const float* __restrict__ inv)
{
    __shared__ float Us[32 * 64];
    __shared__ float Vs[32 * 128];
    int t = threadIdx.x;
    int tx = t & 31, ty = t >> 5;
    int row0 = blockIdx.x * 64;
    float acc[8][4];
#pragma unroll
    for (int i = 0; i < 8; i++)
#pragma unroll
        for (int m = 0; m < 4; m++) acc[i][m] = 0.f;

    for (int c = 0; c < 8; c++) {
        const float* Usrc = (c < 4) ? aggY : hX;
        const float* Wp = (c < 4) ? Wl : Wr;
        int kbase = (c & 3) * 32;
#pragma unroll
        for (int p0 = 0; p0 < 2; p0++) {
            int p = t + p0 * 256;
            int r = p >> 3, kq = p & 7;
            int row = row0 + r;
            float4 u = make_float4(0.f, 0.f, 0.f, 0.f);
            if (row < N_NODES) {
                u = *(const float4*)(Usrc + (size_t)row * H + kbase + kq * 4);
                if (c < 4) { float iv = inv[row]; u.x *= iv; u.y *= iv; u.z *= iv; u.w *= iv; }
            }
            Us[(kq * 4 + 0) * 64 + r] = u.x;
            Us[(kq * 4 + 1) * 64 + r] = u.y;
            Us[(kq * 4 + 2) * 64 + r] = u.z;
            Us[(kq * 4 + 3) * 64 + r] = u.w;
        }
#pragma unroll
        for (int p0 = 0; p0 < 4; p0++) {
            int p = t + p0 * 256;
            int k = p >> 5, jq = p & 31;
            *(float4*)&Vs[k * 128 + jq * 4] = *(const float4*)(Wp + (kbase + k) * H + jq * 4);
        }
        __syncthreads();
#pragma unroll
        for (int kk = 0; kk < 32; kk++) {
            float4 va = *(float4*)&Vs[kk * 128 + tx * 4];
            float4 ua = *(float4*)&Us[kk * 64 + ty * 8];
            float4 ub = *(float4*)&Us[kk * 64 + ty * 8 + 4];
            float u[8] = {ua.x, ua.y, ua.z, ua.w, ub.x, ub.y, ub.z, ub.w};
#pragma unroll
            for (int i = 0; i < 8; i++) {
                acc[i][0] = fmaf(u[i], va.x, acc[i][0]);
                acc[i][1] = fmaf(u[i], va.y, acc[i][1]);
                acc[i][2] = fmaf(u[i], va.z, acc[i][2]);
                acc[i][3] = fmaf(u[i], va.w, acc[i][3]);
            }
        }
        __syncthreads();
    }
    float4 bb = *(const float4*)(bl + tx * 4);
#pragma unroll
    for (int i = 0; i < 8; i++) {
        int row = row0 + ty * 8 + i;
        if (row < N_NODES) {
            float4 o;
            o.x = acc[i][0] + bb.x; o.y = acc[i][1] + bb.y;
            o.z = acc[i][2] + bb.z; o.w = acc[i][3] + bb.w;
            *(float4*)(aggY + (size_t)row * H + tx * 4) = o;
        }
    }
}

// ---------------- LayerNorm + ReLU, warp per row ----------------
__global__ void k_ln(float* __restrict__ h, const float* __restrict__ g,
                     const float* __restrict__ b) {
    int w = (blockIdx.x * blockDim.x + threadIdx.x) >> 5;
    int lane = threadIdx.x & 31;
    if (w >= N_NODES) return;
    float4* p = (float4*)(h + (size_t)w * H);
    float4 v = p[lane];
    float s = v.x + v.y + v.z + v.w;
#pragma unroll
    for (int o = 16; o; o >>= 1) s += __shfl_xor_sync(0xffffffffu, s, o);
    float mu = s * (1.f / 128.f);
    float dx = v.x - mu, dy = v.y - mu, dz = v.z - mu, dw = v.w - mu;
    float q = dx * dx + dy * dy + dz * dz + dw * dw;
#pragma unroll
    for (int o = 16; o; o >>= 1) q += __shfl_xor_sync(0xffffffffu, q, o);
    float rs = rsqrtf(q * (1.f / 128.f) + 1e-5f);
    float4 gg = *(const float4*)(g + lane * 4);
    float4 bv = *(const float4*)(b + lane * 4);
    v.x = fmaxf(fmaf(dx * rs, gg.x, bv.x), 0.f);
    v.y = fmaxf(fmaf(dy * rs, gg.y, bv.y), 0.f);
    v.z = fmaxf(fmaf(dz * rs, gg.z, bv.z), 0.f);
    v.w = fmaxf(fmaf(dw * rs, gg.w, bv.w), 0.f);
    p[lane] = v;
}

// ---------------- Pl = h@W1[0:128]+b1 ; Pr = h@W1[128:256]  (dual GEMM) ----------------
__global__ void __launch_bounds__(256) k_plpr(
    const float* __restrict__ h, const float* __restrict__ W1, const float* __restrict__ b1,
    float* __restrict__ Pl, float* __restrict__ Pr)
{
    __shared__ float Us[32 * 64];
    __shared__ float Vl[32 * 128];
    __shared__ float Vr[32 * 128];
    int t = threadIdx.x;
    int tx = t & 31, ty = t >> 5;
    int row0 = blockIdx.x * 64;
    float accl[8][4], accr[8][4];
#pragma unroll
    for (int i = 0; i < 8; i++)
#pragma unroll
        for (int m = 0; m < 4; m++) { accl[i][m] = 0.f; accr[i][m] = 0.f; }

    for (int c = 0; c < 4; c++) {
        int kbase = c * 32;
#pragma unroll
        for (int p0 = 0; p0 < 2; p0++) {
            int p = t + p0 * 256;
            int r = p >> 3, kq = p & 7;
            int row = row0 + r;
            float4 u = make_float4(0.f, 0.f, 0.f, 0.f);
            if (row < N_NODES)
                u = *(const float4*)(h + (size_t)row * H + kbase + kq * 4);
            Us[(kq * 4 + 0) * 64 + r] = u.x;
            Us[(kq * 4 + 1) * 64 + r] = u.y;
            Us[(kq * 4 + 2) * 64 + r] = u.z;
            Us[(kq * 4 + 3) * 64 + r] = u.w;
        }
#pragma unroll
        for (int p0 = 0; p0 < 4; p0++) {
            int p = t + p0 * 256;
            int k = p >> 5, jq = p & 31;
            *(float4*)&Vl[k * 128 + jq * 4] = *(const float4*)(W1 + (kbase + k) * H + jq * 4);
            *(float4*)&Vr[k * 128 + jq * 4] = *(const float4*)(W1 + (128 + kbase + k) * H + jq * 4);
        }
        __syncthreads();
#pragma unroll
        for (int kk = 0; kk < 32; kk++) {
            float4 va = *(float4*)&Vl[kk * 128 + tx * 4];
            float4 vb = *(float4*)&Vr[kk * 128 + tx * 4];
            float4 ua = *(float4*)&Us[kk * 64 + ty * 8];
            float4 ub = *(float4*)&Us[kk * 64 + ty * 8 + 4];
            float u[8] = {ua.x, ua.y, ua.z, ua.w, ub.x, ub.y, ub.z, ub.w};
#pragma unroll
            for (int i = 0; i < 8; i++) {
                accl[i][0] = fmaf(u[i], va.x, accl[i][0]);
                accl[i][1] = fmaf(u[i], va.y, accl[i][1]);
                accl[i][2] = fmaf(u[i], va.z, accl[i][2]);
                accl[i][3] = fmaf(u[i], va.w, accl[i][3]);
                accr[i][0] = fmaf(u[i], vb.x, accr[i][0]);
                accr[i][1] = fmaf(u[i], vb.y, accr[i][1]);
                accr[i][2] = fmaf(u[i], vb.z, accr[i][2]);
                accr[i][3] = fmaf(u[i], vb.w, accr[i][3]);
            }
        }
        __syncthreads();
    }
    float4 bb = *(const float4*)(b1 + tx * 4);
#pragma unroll
    for (int i = 0; i < 8; i++) {
        int row = row0 + ty * 8 + i;
        if (row < N_NODES) {
            float4 ol, orr;
            ol.x = accl[i][0] + bb.x; ol.y = accl[i][1] + bb.y;
            ol.z = accl[i][2] + bb.z; ol.w = accl[i][3] + bb.w;
            orr.x = accr[i][0]; orr.y = accr[i][1]; orr.z = accr[i][2]; orr.w = accr[i][3];
            *(float4*)(Pl + (size_t)row * H + tx * 4) = ol;
            *(float4*)(Pr + (size_t)row * H + tx * 4) = orr;
        }
    }
}

// ---------------- fused edge MLP ----------------
// TE=64 edges per block, 256 threads.
// Phase1: z1[e][j] = relu(Pl[src]+Pr[dst]+ea@W1e)  -> smem (row stride 132)
// Phase2: warp w owns edges w*8..w*8+7; lane computes outputs {lane, lane+32};
//         z1 loads are warp-broadcast -> FMA-pipe bound.
#define TE 64
#define Z1S (TE * 132)
__global__ void __launch_bounds__(256) k_edge(
    const int* __restrict__ src, const int* __restrict__ dst,
    const float* __restrict__ ea, const float* __restrict__ Pl,
    const float* __restrict__ Pr, const float* __restrict__ W1,
    const float* __restrict__ W2, const float* __restrict__ b2,
    const float* __restrict__ W3, const float* __restrict__ b3,
    float* __restrict__ out)
{
    extern __shared__ float sm[];
    float* z1s = sm;                  // TE*132
    float* W2s = sm + Z1S;            // 128*64
    float* W1es = W2s + 128 * 64;     // 12*128
    float* W3s = W1es + 12 * 128;     // 64
    float* b2s = W3s + 64;            // 64

    int t = threadIdx.x;
    for (int i = t; i < 128 * 64 / 4; i += 256)
        ((float4*)W2s)[i] = ((const float4*)W2)[i];
    for (int i = t; i < 12 * 128 / 4; i += 256)
        ((float4*)W1es)[i] = ((const float4*)(W1 + 256 * H))[i];
    if (t < 64) { W3s[t] = W3[t]; b2s[t] = b2[t]; }

    int e0 = blockIdx.x * TE;
    int el = t >> 2;               // 0..63 local edge
    int jq0 = (t & 3) * 8;         // float4 group base (covers 32 features)
    int eg = e0 + el;
    int s = src[eg], d = dst[eg];
    float eav[12];
#pragma unroll
    for (int k = 0; k < 12; k++) eav[k] = ea[(size_t)eg * 12 + k];
    __syncthreads();   // weights ready

    const float4* pl4 = (const float4*)(Pl + (size_t)s * H);
    const float4* pr4 = (const float4*)(Pr + (size_t)d * H);
#pragma unroll
    for (int jj = 0; jj < 8; jj++) {
        int jqi = jq0 + jj;
        float4 a = pl4[jqi];
        float4 bq = pr4[jqi];
        float4 sv = make_float4(a.x + bq.x, a.y + bq.y, a.z + bq.z, a.w + bq.w);
#pragma unroll
        for (int k = 0; k < 12; k++) {
            float4 w = *(const float4*)&W1es[k * 128 + jqi * 4];
            sv.x = fmaf(eav[k], w.x, sv.x);
            sv.y = fmaf(eav[k], w.y, sv.y);
            sv.z = fmaf(eav[k], w.z, sv.z);
            sv.w = fmaf(eav[k], w.w, sv.w);
        }
        sv.x = fmaxf(sv.x, 0.f); sv.y = fmaxf(sv.y, 0.f);
        sv.z = fmaxf(sv.z, 0.f); sv.w = fmaxf(sv.w, 0.f);
        *(float4*)&z1s[el * 132 + jqi * 4] = sv;
    }
    __syncthreads();

    int warp = t >> 5, lane = t & 31;
    int eb = warp * 8;
    float acc[8][2];
#pragma unroll
    for (int i = 0; i < 8; i++) { acc[i][0] = 0.f; acc[i][1] = 0.f; }
    int o0 = lane, o1 = lane + 32;
#pragma unroll 4
    for (int k = 0; k < 128; k++) {
        float w0 = W2s[k * 64 + o0];
        float w1 = W2s[k * 64 + o1];
#pragma unroll
        for (int i = 0; i < 8; i++) {
            float z = z1s[(eb + i) * 132 + k];
            acc[i][0] = fmaf(z, w0, acc[i][0]);
            acc[i][1] = fmaf(z, w1, acc[i][1]);
        }
    }
    float w3a = W3s[o0], w3b = W3s[o1];
    float bb0 = b2s[o0], bb1 = b2s[o1];
    float pred[8];
#pragma unroll
    for (int i = 0; i < 8; i++) {
        float z2a = fmaxf(acc[i][0] + bb0, 0.f);
        float z2b = fmaxf(acc[i][1] + bb1, 0.f);
        float part = z2a * w3a + z2b * w3b;
#pragma unroll
        for (int o = 16; o; o >>= 1) part += __shfl_xor_sync(0xffffffffu, part, o);
        pred[i] = part;
    }
    if (lane == 0) {
        float b3v = b3[0];
#pragma unroll
        for (int i = 0; i < 8; i++) {
            float x = pred[i] + b3v;
            out[e0 + eb + i] = fmaxf(x, 0.f) + log1pf(expf(-fabsf(x)));
        }
    }
}

// ---------------- launch ----------------
extern "C" void kernel_launch(void* const* d_in, const int* in_sizes, int n_in,
                              void* d_out, int out_size) {
    const float* x      = (const float*)d_in[0];
    const int*   ei     = (const int*)d_in[1];
    const float* ea     = (const float*)d_in[2];
    const float* node_W = (const float*)d_in[3];
    const float* node_b = (const float*)d_in[4];
    const float* sWl    = (const float*)d_in[5];
    const float* sbl    = (const float*)d_in[6];
    const float* sWr    = (const float*)d_in[7];
    const float* ln_g   = (const float*)d_in[8];
    const float* ln_b   = (const float*)d_in[9];
    const float* W1     = (const float*)d_in[10];
    const float* b1     = (const float*)d_in[11];
    const float* W2     = (const float*)d_in[12];
    const float* b2     = (const float*)d_in[13];
    const float* W3     = (const float*)d_in[14];
    const float* b3     = (const float*)d_in[15];
    float* out = (float*)d_out;
    const int* src = ei;
    const int* dstp = ei + N_EDGES;

    float *pA, *pB, *pPl, *pPr, *pInv;
    cudaGetSymbolAddress((void**)&pA, g_bufA);
    cudaGetSymbolAddress((void**)&pB, g_bufB);
    cudaGetSymbolAddress((void**)&pPl, g_Pl);
    cudaGetSymbolAddress((void**)&pPr, g_Pr);
    cudaGetSymbolAddress((void**)&pInv, g_inv);

    cudaMemsetAsync(pInv, 0, N_NODES * sizeof(float));
    k_deg<<<(N_EDGES + 255) / 256, 256>>>(dstp, pInv);
    k_inv<<<(N_NODES + 255) / 256, 256>>>(pInv);

    k_nodeproj<<<(N_NODES * H + 255) / 256, 256>>>(x, node_W, node_b, pA);

    float* hcur = pA;
    float* other = pB;
    for (int l = 0; l < 3; l++) {
        cudaMemsetAsync(other, 0, (size_t)N_NODES * H * sizeof(float));
        k_scatter<<<N_EDGES / 8, 256>>>(src, dstp, hcur, other);
        k_sage<<<(N_NODES + 63) / 64, 256>>>(hcur, other, sWl + l * HH, sbl + l * H,
                                             sWr + l * HH, pInv);
        k_ln<<<(N_NODES + 7) / 8, 256>>>(other, ln_g + l * H, ln_b + l * H);
        float* tmp = hcur; hcur = other; other = tmp;
    }

    k_plpr<<<(N_NODES + 63) / 64, 256>>>(hcur, W1, b1, pPl, pPr);

    int smem_edge = (Z1S + 128 * 64 + 12 * 128 + 128) * sizeof(float);
    cudaFuncSetAttribute(k_edge, cudaFuncAttributeMaxDynamicSharedMemorySize, smem_edge);
    k_edge<<<N_EDGES / TE, 256, smem_edge>>>(src, dstp, ea, pPl, pPr, W1, W2, b2, W3, b3, out);
}